// round 11
// baseline (speedup 1.0000x reference)
#include <cuda_runtime.h>
#include <cuda_bf16.h>
#include <cstddef>
#include <cstdint>

#define HDIM 1024
#define SLEN 4096
#define BATCH 32
#define NSB 8                              // s-blocks per batch = cluster size
#define ROWS_PER_BLOCK (SLEN / NSB)        // 512
#define NWARPS 8
#define ROWS_PER_WARP (ROWS_PER_BLOCK / NWARPS)  // 64

// Scratch (device globals; no allocation in kernel_launch)
__device__ float g_vprime[HDIM];                   // U^T V

// ---------------- smem / cluster helpers ----------------
__device__ __forceinline__ uint32_t smem_u32(const void* p) {
    return (uint32_t)__cvta_generic_to_shared(p);
}
__device__ __forceinline__ uint32_t mapa_rank(uint32_t addr, uint32_t rank) {
    uint32_t r;
    asm("mapa.shared::cluster.u32 %0, %1, %2;" : "=r"(r) : "r"(addr), "r"(rank));
    return r;
}
__device__ __forceinline__ float2 ld_dsmem_f2(uint32_t a) {
    float2 v;
    asm volatile("ld.shared::cluster.v2.f32 {%0,%1}, [%2];"
                 : "=f"(v.x), "=f"(v.y) : "r"(a));
    return v;
}
__device__ __forceinline__ float4 ld_dsmem_f4(uint32_t a) {
    float4 v;
    asm volatile("ld.shared::cluster.v4.f32 {%0,%1,%2,%3}, [%4];"
                 : "=f"(v.x), "=f"(v.y), "=f"(v.z), "=f"(v.w) : "r"(a));
    return v;
}
// volatile LDS.128: cannot be hoisted out of the loop by the compiler
__device__ __forceinline__ float4 lds_f4(uint32_t a) {
    float4 v;
    asm volatile("ld.shared.v4.f32 {%0,%1,%2,%3}, [%4];"
                 : "=f"(v.x), "=f"(v.y), "=f"(v.z), "=f"(v.w) : "r"(a));
    return v;
}
#define CLUSTER_ARRIVE() asm volatile("barrier.cluster.arrive.aligned;" ::: "memory")
#define CLUSTER_WAIT()   asm volatile("barrier.cluster.wait.aligned;" ::: "memory")
#define CLUSTER_SYNC() do { CLUSTER_ARRIVE(); CLUSTER_WAIT(); } while (0)

// ---------------------------------------------------------------------------
// K1 (fused): v'[h] = sum_o U[o,h] * V[o], single kernel.
// grid 128, block 256. Block: 8 h-columns; thread (h_off = t&7, o_idx = t>>3)
// accumulates 32 strided o-rows, then smem tree reduce.
// ---------------------------------------------------------------------------
__global__ void vprime_fused_kernel(const float* __restrict__ U,
                                    const float* __restrict__ V) {
    const int t     = threadIdx.x;
    const int h_off = t & 7;
    const int o_idx = t >> 3;              // 0..31
    const int h0    = blockIdx.x * 8;

    __shared__ float sm[256];

    float acc = 0.0f;
#pragma unroll 8
    for (int it = 0; it < 32; it++) {
        const int o = it * 32 + o_idx;
        acc += U[(size_t)o * HDIM + h0 + h_off] * __ldg(&V[o]);
    }
    sm[t] = acc;
    __syncthreads();

#pragma unroll
    for (int s = 128; s >= 8; s >>= 1) {
        if (t < s) sm[t] += sm[t + s];
        __syncthreads();
    }
    if (t < 8) g_vprime[h0 + t] = sm[t];
}

// ---------------------------------------------------------------------------
// K2: fused streaming pass (keys read once, __ldcs) + cluster epilogue.
// occ 3 (regs <= 85): single-row loop with 8 front-batched LDG.128; the
// extra resident CTAs/SM supply the in-flight bytes the interleave used to.
// v' in SMEM via volatile LDS (no register hoist).
// grid (NSB, BATCH), cluster (NSB,1,1), block 256.
// out layout: [context B*H | weight B*S]
// ---------------------------------------------------------------------------
__global__ void __launch_bounds__(256, 3) __cluster_dims__(NSB, 1, 1)
main_pass_kernel(const float* __restrict__ keys, float* __restrict__ out) {
    const int b    = blockIdx.y;
    const int sb   = blockIdx.x;          // == cluster rank
    const int w    = threadIdx.x >> 5;
    const int lane = threadIdx.x & 31;
    const int t    = threadIdx.x;

    __shared__ float4 s_vp[256];               // 4 KB v'
    __shared__ float4 s_acc[NWARPS][256];      // 32 KB warp partials
    __shared__ float  s_m[NWARPS];
    __shared__ float  s_l[NWARPS];
    __shared__ float4 s_bacc[256];             // 4 KB block partial acc
    __shared__ float2 s_ml;                    // block partial (M, L)
    __shared__ float  s_scores[ROWS_PER_BLOCK];// 2 KB raw scores
    __shared__ float  s_pm[NSB], s_pl[NSB];    // gathered peer M/L

    s_vp[t] = reinterpret_cast<const float4*>(g_vprime)[t];
    __syncthreads();

    float m = -3.0e38f;
    float l = 0.0f;
    float4 acc[8];
#pragma unroll
    for (int i = 0; i < 8; i++) acc[i] = make_float4(0.f, 0.f, 0.f, 0.f);

    const int s0 = sb * ROWS_PER_BLOCK + w * ROWS_PER_WARP;
    const float4* __restrict__ base =
        reinterpret_cast<const float4*>(keys + (size_t)b * SLEN * HDIM)
        + (size_t)s0 * (HDIM / 4) + lane;
    const uint32_t vp_base = smem_u32(&s_vp[lane]);   // +i*32*16 per step
    float* __restrict__ w_scores = &s_scores[w * ROWS_PER_WARP];

    for (int j = 0; j < ROWS_PER_WARP; j++) {
        const float4* __restrict__ row = base + (size_t)j * (HDIM / 4);

        float4 k[8];
#pragma unroll
        for (int i = 0; i < 8; i++) k[i] = __ldcs(row + i * 32);

        float d = 0.0f;
#pragma unroll
        for (int i = 0; i < 8; i++) {
            const float4 vp = lds_f4(vp_base + (uint32_t)(i * 32) * 16u);
            d += k[i].x * vp.x + k[i].y * vp.y +
                 k[i].z * vp.z + k[i].w * vp.w;
        }
#pragma unroll
        for (int off = 16; off; off >>= 1)
            d += __shfl_xor_sync(0xffffffffu, d, off);

        if (lane == 0) w_scores[j] = d;

        if (d > m) {              // warp-uniform, rare
            const float sc = __expf(m - d);
            l *= sc;
#pragma unroll
            for (int i = 0; i < 8; i++) {
                acc[i].x *= sc; acc[i].y *= sc;
                acc[i].z *= sc; acc[i].w *= sc;
            }
            m = d;
        }
        const float p = __expf(d - m);
        l += p;
#pragma unroll
        for (int i = 0; i < 8; i++) {
            acc[i].x += p * k[i].x; acc[i].y += p * k[i].y;
            acc[i].z += p * k[i].z; acc[i].w += p * k[i].w;
        }
    }

    // ---- block-level merge of 8 warp partials (smem) ----
#pragma unroll
    for (int i = 0; i < 8; i++) s_acc[w][i * 32 + lane] = acc[i];
    if (lane == 0) { s_m[w] = m; s_l[w] = l; }
    __syncthreads();

    float Mb = s_m[0];
#pragma unroll
    for (int ww = 1; ww < NWARPS; ww++) Mb = fmaxf(Mb, s_m[ww]);
    float Lb = 0.0f;
    float scale[NWARPS];
#pragma unroll
    for (int ww = 0; ww < NWARPS; ww++) {
        scale[ww] = __expf(s_m[ww] - Mb);
        Lb += scale[ww] * s_l[ww];
    }

    float4 bsum = make_float4(0.f, 0.f, 0.f, 0.f);
#pragma unroll
    for (int ww = 0; ww < NWARPS; ww++) {
        float4 v = s_acc[ww][t];
        const float sc = scale[ww];
        bsum.x += sc * v.x; bsum.y += sc * v.y;
        bsum.z += sc * v.z; bsum.w += sc * v.w;
    }
    s_bacc[t] = bsum;
    if (t == 0) { s_ml.x = Mb; s_ml.y = Lb; }
    __syncthreads();

    // ---- cluster-wide merge via DSMEM ----
    CLUSTER_SYNC();

    if (t < NSB) {
        uint32_t a = mapa_rank(smem_u32(&s_ml), (uint32_t)t);
        float2 ml = ld_dsmem_f2(a);
        s_pm[t] = ml.x; s_pl[t] = ml.y;
    }
    __syncthreads();

    float M = s_pm[0];
#pragma unroll
    for (int p = 1; p < NSB; p++) M = fmaxf(M, s_pm[p]);
    float L = 0.0f;
    float scg[NSB];
#pragma unroll
    for (int p = 0; p < NSB; p++) {
        scg[p] = __expf(s_pm[p] - M);
        L += scg[p] * s_pl[p];
    }
    const float invL = 1.0f / L;

    // context slice: this CTA owns float4 columns [sb*32, sb*32+32)
    if (t < 32) {
        const int h4 = sb * 32 + t;
        const uint32_t loc = smem_u32(&s_bacc[h4]);
        float4 cs = make_float4(0.f, 0.f, 0.f, 0.f);
#pragma unroll
        for (int p = 0; p < NSB; p++) {
            float4 v = ld_dsmem_f4(mapa_rank(loc, (uint32_t)p));
            cs.x += scg[p] * v.x; cs.y += scg[p] * v.y;
            cs.z += scg[p] * v.z; cs.w += scg[p] * v.w;
        }
        cs.x *= invL; cs.y *= invL; cs.z *= invL; cs.w *= invL;
        reinterpret_cast<float4*>(out + (size_t)b * HDIM)[h4] = cs;
    }

    // all cross-CTA reads done (context write above consumed them)
    CLUSTER_ARRIVE();

    // weights for this CTA's 512 rows — overlaps peers' epilogues
    float* __restrict__ wout =
        out + (size_t)BATCH * HDIM + (size_t)b * SLEN + (size_t)sb * ROWS_PER_BLOCK;
#pragma unroll
    for (int i = 0; i < ROWS_PER_BLOCK / 256; i++) {
        const int s = i * 256 + t;
        wout[s] = __expf(s_scores[s] - M) * invL;
    }

    // keep SMEM alive until all peers finished their DSMEM reads
    CLUSTER_WAIT();
}

// ---------------------------------------------------------------------------
extern "C" void kernel_launch(void* const* d_in, const int* in_sizes, int n_in,
                              void* d_out, int out_size) {
    // inputs (metadata order): query, keys, W, U, V
    const float* keys = (const float*)d_in[1];
    const float* U    = (const float*)d_in[3];
    const float* V    = (const float*)d_in[4];
    float* out = (float*)d_out;

    vprime_fused_kernel<<<128, 256>>>(U, V);
    main_pass_kernel<<<dim3(NSB, BATCH), 256>>>(keys, out);
}

// round 12
// speedup vs baseline: 1.2339x; 1.2339x over previous
#include <cuda_runtime.h>
#include <cuda_bf16.h>
#include <cstddef>
#include <cstdint>

#define HDIM 1024
#define SLEN 4096
#define BATCH 32
#define NSB 8                              // s-blocks per batch = cluster size
#define ROWS_PER_BLOCK (SLEN / NSB)        // 512
#define NWARPS 8
#define ROWS_PER_WARP (ROWS_PER_BLOCK / NWARPS)  // 64
#define HALF_RPW (ROWS_PER_WARP / 2)       // 32

// Scratch (device globals; no allocation in kernel_launch)
__device__ float g_vprime[HDIM];                   // U^T V

// ---------------- smem / cluster helpers ----------------
__device__ __forceinline__ uint32_t smem_u32(const void* p) {
    return (uint32_t)__cvta_generic_to_shared(p);
}
__device__ __forceinline__ uint32_t mapa_rank(uint32_t addr, uint32_t rank) {
    uint32_t r;
    asm("mapa.shared::cluster.u32 %0, %1, %2;" : "=r"(r) : "r"(addr), "r"(rank));
    return r;
}
__device__ __forceinline__ float2 ld_dsmem_f2(uint32_t a) {
    float2 v;
    asm volatile("ld.shared::cluster.v2.f32 {%0,%1}, [%2];"
                 : "=f"(v.x), "=f"(v.y) : "r"(a));
    return v;
}
__device__ __forceinline__ float4 ld_dsmem_f4(uint32_t a) {
    float4 v;
    asm volatile("ld.shared::cluster.v4.f32 {%0,%1,%2,%3}, [%4];"
                 : "=f"(v.x), "=f"(v.y), "=f"(v.z), "=f"(v.w) : "r"(a));
    return v;
}
// volatile LDS.128: cannot be hoisted out of the loop by the compiler
__device__ __forceinline__ float4 lds_f4(uint32_t a) {
    float4 v;
    asm volatile("ld.shared.v4.f32 {%0,%1,%2,%3}, [%4];"
                 : "=f"(v.x), "=f"(v.y), "=f"(v.z), "=f"(v.w) : "r"(a));
    return v;
}
#define CLUSTER_ARRIVE() asm volatile("barrier.cluster.arrive.aligned;" ::: "memory")
#define CLUSTER_WAIT()   asm volatile("barrier.cluster.wait.aligned;" ::: "memory")
#define CLUSTER_SYNC() do { CLUSTER_ARRIVE(); CLUSTER_WAIT(); } while (0)

// ---------------------------------------------------------------------------
// K1 (fused): v'[h] = sum_o U[o,h] * V[o], single kernel.
// grid 128, block 256. Triggers PDL completion after its stores.
// ---------------------------------------------------------------------------
__global__ void vprime_fused_kernel(const float* __restrict__ U,
                                    const float* __restrict__ V) {
    const int t     = threadIdx.x;
    const int h_off = t & 7;
    const int o_idx = t >> 3;              // 0..31
    const int h0    = blockIdx.x * 8;

    __shared__ float sm[256];

    float acc = 0.0f;
#pragma unroll 8
    for (int it = 0; it < 32; it++) {
        const int o = it * 32 + o_idx;
        acc += U[(size_t)o * HDIM + h0 + h_off] * __ldg(&V[o]);
    }
    sm[t] = acc;
    __syncthreads();

#pragma unroll
    for (int s = 128; s >= 8; s >>= 1) {
        if (t < s) sm[t] += sm[t + s];
        __syncthreads();
    }
    if (t < 8) g_vprime[h0 + t] = sm[t];

#if __CUDA_ARCH__ >= 900
    cudaTriggerProgrammaticLaunchCompletion();
#endif
}

// ---------------------------------------------------------------------------
// K2: fused streaming pass (keys read once, __ldcs) + cluster epilogue.
// R10 mainloop (protected): row-pair interleave, 16 front-batched LDG.128,
// v' in SMEM via volatile LDS, occ 2. Launched with PDL: CTAs spawn during
// vprime, set up, then grid-dep-sync before reading g_vprime.
// grid (NSB, BATCH), cluster (NSB,1,1), block 256.
// out layout: [context B*H | weight B*S]
// ---------------------------------------------------------------------------
__global__ void __launch_bounds__(256, 2) __cluster_dims__(NSB, 1, 1)
main_pass_kernel(const float* __restrict__ keys, float* __restrict__ out) {
    const int b    = blockIdx.y;
    const int sb   = blockIdx.x;          // == cluster rank
    const int w    = threadIdx.x >> 5;
    const int lane = threadIdx.x & 31;
    const int t    = threadIdx.x;

    __shared__ float4 s_vp[256];               // 4 KB v'
    __shared__ float4 s_acc[NWARPS][256];      // 32 KB warp partials
    __shared__ float  s_m[NWARPS];
    __shared__ float  s_l[NWARPS];
    __shared__ float4 s_bacc[256];             // 4 KB block partial acc
    __shared__ float2 s_ml;                    // block partial (M, L)
    __shared__ float  s_scores[ROWS_PER_BLOCK];// 2 KB raw scores
    __shared__ float  s_pm[NSB], s_pl[NSB];    // gathered peer M/L

    // wait for vprime's stores to be visible, then pull v' into smem
#if __CUDA_ARCH__ >= 900
    cudaGridDependencySynchronize();
#endif
    s_vp[t] = reinterpret_cast<const float4*>(g_vprime)[t];
    __syncthreads();

    float m = -3.0e38f;
    float l = 0.0f;
    float4 acc[8];
#pragma unroll
    for (int i = 0; i < 8; i++) acc[i] = make_float4(0.f, 0.f, 0.f, 0.f);

    const int s0 = sb * ROWS_PER_BLOCK + w * ROWS_PER_WARP;
    const float4* __restrict__ base =
        reinterpret_cast<const float4*>(keys + (size_t)b * SLEN * HDIM)
        + (size_t)s0 * (HDIM / 4) + lane;
    const uint32_t vp_base = smem_u32(&s_vp[lane]);   // +i*32*16 per step
    float* __restrict__ w_scores = &s_scores[w * ROWS_PER_WARP];

    for (int j = 0; j < HALF_RPW; j++) {
        const float4* __restrict__ rA = base + (size_t)j * (HDIM / 4);
        const float4* __restrict__ rB = rA + (size_t)HALF_RPW * (HDIM / 4);

        float4 k1[8], k2[8];
#pragma unroll
        for (int i = 0; i < 8; i++) k1[i] = __ldcs(rA + i * 32);
#pragma unroll
        for (int i = 0; i < 8; i++) k2[i] = __ldcs(rB + i * 32);

        float d1 = 0.0f, d2 = 0.0f;
#pragma unroll
        for (int i = 0; i < 8; i++) {
            const float4 vp = lds_f4(vp_base + (uint32_t)(i * 32) * 16u);
            d1 += k1[i].x * vp.x + k1[i].y * vp.y +
                  k1[i].z * vp.z + k1[i].w * vp.w;
            d2 += k2[i].x * vp.x + k2[i].y * vp.y +
                  k2[i].z * vp.z + k2[i].w * vp.w;
        }
#pragma unroll
        for (int off = 16; off; off >>= 1) {
            d1 += __shfl_xor_sync(0xffffffffu, d1, off);
            d2 += __shfl_xor_sync(0xffffffffu, d2, off);
        }

        if (lane == 0) {
            w_scores[j]            = d1;
            w_scores[j + HALF_RPW] = d2;
        }

        const float mNew = fmaxf(m, fmaxf(d1, d2));
        if (mNew > m) {           // warp-uniform, rare
            const float sc = __expf(m - mNew);
            l *= sc;
#pragma unroll
            for (int i = 0; i < 8; i++) {
                acc[i].x *= sc; acc[i].y *= sc;
                acc[i].z *= sc; acc[i].w *= sc;
            }
            m = mNew;
        }
        const float p1 = __expf(d1 - m);
        const float p2 = __expf(d2 - m);
        l += p1 + p2;
#pragma unroll
        for (int i = 0; i < 8; i++) {
            acc[i].x += p1 * k1[i].x + p2 * k2[i].x;
            acc[i].y += p1 * k1[i].y + p2 * k2[i].y;
            acc[i].z += p1 * k1[i].z + p2 * k2[i].z;
            acc[i].w += p1 * k1[i].w + p2 * k2[i].w;
        }
    }

    // ---- block-level merge of 8 warp partials (smem) ----
#pragma unroll
    for (int i = 0; i < 8; i++) s_acc[w][i * 32 + lane] = acc[i];
    if (lane == 0) { s_m[w] = m; s_l[w] = l; }
    __syncthreads();

    float Mb = s_m[0];
#pragma unroll
    for (int ww = 1; ww < NWARPS; ww++) Mb = fmaxf(Mb, s_m[ww]);
    float Lb = 0.0f;
    float scale[NWARPS];
#pragma unroll
    for (int ww = 0; ww < NWARPS; ww++) {
        scale[ww] = __expf(s_m[ww] - Mb);
        Lb += scale[ww] * s_l[ww];
    }

    float4 bsum = make_float4(0.f, 0.f, 0.f, 0.f);
#pragma unroll
    for (int ww = 0; ww < NWARPS; ww++) {
        float4 v = s_acc[ww][t];
        const float sc = scale[ww];
        bsum.x += sc * v.x; bsum.y += sc * v.y;
        bsum.z += sc * v.z; bsum.w += sc * v.w;
    }
    s_bacc[t] = bsum;
    if (t == 0) { s_ml.x = Mb; s_ml.y = Lb; }
    __syncthreads();

    // ---- cluster-wide merge via DSMEM ----
    CLUSTER_SYNC();

    if (t < NSB) {
        uint32_t a = mapa_rank(smem_u32(&s_ml), (uint32_t)t);
        float2 ml = ld_dsmem_f2(a);
        s_pm[t] = ml.x; s_pl[t] = ml.y;
    }
    __syncthreads();

    float M = s_pm[0];
#pragma unroll
    for (int p = 1; p < NSB; p++) M = fmaxf(M, s_pm[p]);
    float L = 0.0f;
    float scg[NSB];
#pragma unroll
    for (int p = 0; p < NSB; p++) {
        scg[p] = __expf(s_pm[p] - M);
        L += scg[p] * s_pl[p];
    }
    const float invL = 1.0f / L;

    // context slice: this CTA owns float4 columns [sb*32, sb*32+32)
    if (t < 32) {
        const int h4 = sb * 32 + t;
        const uint32_t loc = smem_u32(&s_bacc[h4]);
        float4 cs = make_float4(0.f, 0.f, 0.f, 0.f);
#pragma unroll
        for (int p = 0; p < NSB; p++) {
            float4 v = ld_dsmem_f4(mapa_rank(loc, (uint32_t)p));
            cs.x += scg[p] * v.x; cs.y += scg[p] * v.y;
            cs.z += scg[p] * v.z; cs.w += scg[p] * v.w;
        }
        cs.x *= invL; cs.y *= invL; cs.z *= invL; cs.w *= invL;
        reinterpret_cast<float4*>(out + (size_t)b * HDIM)[h4] = cs;
    }

    // all cross-CTA reads done (context write above consumed them)
    CLUSTER_ARRIVE();

    // weights for this CTA's 512 rows — overlaps peers' epilogues
    float* __restrict__ wout =
        out + (size_t)BATCH * HDIM + (size_t)b * SLEN + (size_t)sb * ROWS_PER_BLOCK;
#pragma unroll
    for (int i = 0; i < ROWS_PER_BLOCK / 256; i++) {
        const int s = i * 256 + t;
        wout[s] = __expf(s_scores[s] - M) * invL;
    }

    // keep SMEM alive until all peers finished their DSMEM reads
    CLUSTER_WAIT();
}

// ---------------------------------------------------------------------------
extern "C" void kernel_launch(void* const* d_in, const int* in_sizes, int n_in,
                              void* d_out, int out_size) {
    // inputs (metadata order): query, keys, W, U, V
    const float* keys = (const float*)d_in[1];
    const float* U    = (const float*)d_in[3];
    const float* V    = (const float*)d_in[4];
    float* out = (float*)d_out;

    vprime_fused_kernel<<<128, 256>>>(U, V);

    // main pass with PDL: overlap its CTA spawn/setup with vprime
    cudaLaunchConfig_t cfg = {};
    cfg.gridDim  = dim3(NSB, BATCH, 1);
    cfg.blockDim = dim3(256, 1, 1);
    cudaLaunchAttribute attrs[1];
    attrs[0].id = cudaLaunchAttributeProgrammaticStreamSerialization;
    attrs[0].val.programmaticStreamSerializationAllowed = 1;
    cfg.attrs = attrs;
    cfg.numAttrs = 1;
    cudaLaunchKernelEx(&cfg, main_pass_kernel, keys, out);
}